// round 9
// baseline (speedup 1.0000x reference)
#include <cuda_runtime.h>
#include <cuda_bf16.h>
#include <cstdint>

#define Dh 128
#define DINx 64
#define NLV 15
#define EMAX 20480
#define NPMAX 8192
#define TILE_E 64
#define TILE_G 32

__device__ float g_msg[NPMAX * Dh];
__device__ int g_eperm[NLV * EMAX];
__device__ int g_nperm[NLV * NPMAX];
__device__ int g_ecnt[NLV][5], g_ncnt[NLV][5];
__device__ int g_ecur[NLV][5], g_ncur[NLV][5];
__device__ int g_eoff[NLV][5], g_noff[NLV][5];
__device__ int g_etile[NLV][6], g_ntile[NLV][6];
__device__ int g_done;

__device__ __nv_bfloat16 g_W1h[5 * 256 * 128], g_W1l[5 * 256 * 128];
__device__ __nv_bfloat16 g_W2h[5 * 128 * 128], g_W2l[5 * 128 * 128];
__device__ __nv_bfloat16 g_W3h[5 * 128 * 128], g_W3l[5 * 128 * 128];
__device__ __nv_bfloat16 g_Wih_h[5 * 128 * 384], g_Wih_l[5 * 128 * 384];
__device__ __nv_bfloat16 g_Whh_h[5 * 128 * 384], g_Whh_l[5 * 128 * 384];

__constant__ int c_TI[6] = {0, 3, 1, 0, 4, 2};

__device__ __forceinline__ float sigmf(float x) { return 1.f / (1.f + __expf(-x)); }
__device__ __forceinline__ float tanhff(float x) { float e = __expf(2.f * x); return 1.f - 2.f / (e + 1.f); }

__device__ __forceinline__ void splitbf(float v, __nv_bfloat16* h, __nv_bfloat16* l) {
    __nv_bfloat16 hh = __float2bfloat16_rn(v);
    *h = hh;
    *l = __float2bfloat16_rn(v - __bfloat162float(hh));
}

__device__ __forceinline__ void ldsm4(uint32_t r[4], const void* p) {
    unsigned int a = (unsigned int)__cvta_generic_to_shared(p);
    asm volatile("ldmatrix.sync.aligned.m8n8.x4.shared.b16 {%0,%1,%2,%3},[%4];"
                 : "=r"(r[0]), "=r"(r[1]), "=r"(r[2]), "=r"(r[3]) : "r"(a));
}
__device__ __forceinline__ void ldsm4t(uint32_t r[4], const void* p) {
    unsigned int a = (unsigned int)__cvta_generic_to_shared(p);
    asm volatile("ldmatrix.sync.aligned.m8n8.x4.trans.shared.b16 {%0,%1,%2,%3},[%4];"
                 : "=r"(r[0]), "=r"(r[1]), "=r"(r[2]), "=r"(r[3]) : "r"(a));
}
__device__ __forceinline__ void mma_bf(float c[4], const uint32_t a[4], uint32_t b0, uint32_t b1) {
    asm volatile(
        "mma.sync.aligned.m16n8k16.row.col.f32.bf16.bf16.f32 "
        "{%0,%1,%2,%3},{%4,%5,%6,%7},{%8,%9},{%0,%1,%2,%3};"
        : "+f"(c[0]), "+f"(c[1]), "+f"(c[2]), "+f"(c[3])
        : "r"(a[0]), "r"(a[1]), "r"(a[2]), "r"(a[3]), "r"(b0), "r"(b1));
}
__device__ __forceinline__ void cpa16(void* smem, const void* gmem) {
    unsigned int a = (unsigned int)__cvta_generic_to_shared(smem);
    asm volatile("cp.async.ca.shared.global [%0],[%1],16;" :: "r"(a), "l"(gmem));
}
__device__ __forceinline__ void cp_commit() { asm volatile("cp.async.commit_group;"); }
template<int N> __device__ __forceinline__ void cp_wait() { asm volatile("cp.async.wait_group %0;" :: "n"(N)); }

// ---------------- launch 1: zero + counters + weight split ----------------
__global__ __launch_bounds__(256) void k_prep(const float* __restrict__ aW1, const float* __restrict__ aW2,
                                              const float* __restrict__ aW3, const float* __restrict__ gWih,
                                              const float* __restrict__ gWhh) {
    int i = blockIdx.x * 256 + threadIdx.x;
    if (i == 0) g_done = 0;
    if (i < NPMAX * Dh) g_msg[i] = 0.f;
    if (i < NLV * 5) {
        ((int*)g_ecnt)[i] = 0; ((int*)g_ncnt)[i] = 0;
        ((int*)g_ecur)[i] = 0; ((int*)g_ncur)[i] = 0;
    }
    if (i < 163840) splitbf(aW1[i], &g_W1h[i], &g_W1l[i]);
    else if (i < 245760) { int j = i - 163840; splitbf(aW2[j], &g_W2h[j], &g_W2l[j]); }
    else if (i < 327680) { int j = i - 245760; splitbf(aW3[j], &g_W3h[j], &g_W3l[j]); }
    else if (i < 573440) { int j = i - 327680; splitbf(gWih[j], &g_Wih_h[j], &g_Wih_l[j]); }
    else if (i < 819200) { int j = i - 573440; splitbf(gWhh[j], &g_Whh_h[j], &g_Whh_l[j]); }
}

// ---------------- launch 2: count + (last block) scan ----------------
__global__ __launch_bounds__(256) void k_countscan(const int* __restrict__ eg, const int* __restrict__ ng, int Epad, int NP) {
    __shared__ int hist[150];
    __shared__ int s_ticket;
    int tid = threadIdx.x;
    if (tid < 150) hist[tid] = 0;
    __syncthreads();
    int i = blockIdx.x * 256 + tid;
    int ne = NLV * Epad;
    if (i < ne) {
        int g = eg[i];
        if (g > 0) atomicAdd(&hist[(i / Epad) * 5 + g - 1], 1);
    } else {
        int j = i - ne;
        if (j < NLV * NP) {
            int g = ng[j];
            if (g > 0) atomicAdd(&hist[75 + (j / NP) * 5 + g - 1], 1);
        }
    }
    __syncthreads();
    if (tid < 75 && hist[tid]) atomicAdd(&((int*)g_ecnt)[tid], hist[tid]);
    if (tid >= 75 && tid < 150 && hist[tid]) atomicAdd(&((int*)g_ncnt)[tid - 75], hist[tid]);
    __threadfence();
    __syncthreads();
    if (tid == 0) s_ticket = atomicAdd(&g_done, 1);
    __syncthreads();
    if (s_ticket == (int)gridDim.x - 1 && tid < NLV) {
        int l = tid;
        int off = 0, to = 0;
        for (int t = 0; t < 5; t++) {
            int cnt = atomicAdd(&g_ecnt[l][t], 0);
            g_eoff[l][t] = off; g_etile[l][t] = to;
            off += cnt; to += (cnt + TILE_E - 1) / TILE_E;
        }
        g_etile[l][5] = to;
        off = 0; to = 0;
        for (int t = 0; t < 5; t++) {
            int cnt = atomicAdd(&g_ncnt[l][t], 0);
            g_noff[l][t] = off; g_ntile[l][t] = to;
            off += cnt; to += (cnt + TILE_G - 1) / TILE_G;
        }
        g_ntile[l][5] = to;
    }
}

// ---------------- launch 3: fused scatter + input projections ----------------
__global__ __launch_bounds__(256)
void k_si(const int* __restrict__ eg, const int* __restrict__ ng, int Epad, int NP, int SC,
          const float* __restrict__ x, const float* __restrict__ Ws, const float* __restrict__ Wt,
          float* __restrict__ sb, float* __restrict__ tb, float* __restrict__ hb, int N) {
    extern __shared__ float smf[];
    int tid = threadIdx.x;
    if (blockIdx.x < SC) {
        int* hist = (int*)smf;
        int* basev = hist + 150;
        int* lcur = basev + 150;
        if (tid < 150) { hist[tid] = 0; lcur[tid] = 0; }
        __syncthreads();
        int i = blockIdx.x * 256 + tid;
        int ne = NLV * Epad;
        int bin = -1;
        if (i < ne) {
            int g = eg[i];
            if (g > 0) bin = (i / Epad) * 5 + g - 1;
        } else {
            int j = i - ne;
            if (j < NLV * NP) {
                int g = ng[j];
                if (g > 0) bin = 75 + (j / NP) * 5 + g - 1;
            }
        }
        if (bin >= 0) atomicAdd(&hist[bin], 1);
        __syncthreads();
        if (tid < 75 && hist[tid]) basev[tid] = atomicAdd(&((int*)g_ecur)[tid], hist[tid]);
        if (tid >= 75 && tid < 150 && hist[tid]) basev[tid] = atomicAdd(&((int*)g_ncur)[tid - 75], hist[tid]);
        __syncthreads();
        if (bin >= 0) {
            int p = basev[bin] + atomicAdd(&lcur[bin], 1);
            if (bin < 75) {
                int l = bin / 5;
                g_eperm[l * EMAX + ((int*)g_eoff)[bin] + p] = i % Epad;
            } else {
                int l = (bin - 75) / 5;
                g_nperm[l * NPMAX + ((int*)g_noff)[bin - 75] + p] = (i - ne) % NP;
            }
        }
        return;
    }
    // ---- input projection part ----
    float* smx = smf;
    float* sws = smf + 4096;
    float* swt = sws + 8192;
    int row0 = (blockIdx.x - SC) * 64;
    for (int i = tid; i < 8192; i += 256) { sws[i] = Ws[i]; swt[i] = Wt[i]; }
    for (int i = tid; i < 4096; i += 256) {
        int r = i >> 6, gr = row0 + r;
        smx[i] = (gr < N) ? x[gr * DINx + (i & 63)] : 0.f;
    }
    __syncthreads();
    int tx = tid & 31, ty = tid >> 5;
    float as[8][4] = {}, at[8][4] = {};
    #pragma unroll 4
    for (int k = 0; k < 64; k++) {
        float4 bs = *(float4*)&sws[k * 128 + tx * 4];
        float4 bt = *(float4*)&swt[k * 128 + tx * 4];
        #pragma unroll
        for (int r = 0; r < 8; r++) {
            float a = smx[(ty * 8 + r) * 64 + k];
            as[r][0] += a * bs.x; as[r][1] += a * bs.y; as[r][2] += a * bs.z; as[r][3] += a * bs.w;
            at[r][0] += a * bt.x; at[r][1] += a * bt.y; at[r][2] += a * bt.z; at[r][3] += a * bt.w;
        }
    }
    #pragma unroll
    for (int r = 0; r < 8; r++) {
        int gr = row0 + ty * 8 + r;
        if (gr < N) {
            *(float4*)&sb[gr * Dh + tx * 4] = make_float4(as[r][0], as[r][1], as[r][2], as[r][3]);
            *(float4*)&tb[gr * Dh + tx * 4] = make_float4(at[r][0], at[r][1], at[r][2], at[r][3]);
            *(float4*)&hb[gr * Dh + tx * 4] = make_float4(0.f, 0.f, 0.f, 0.f);
        }
    }
}

// ---------------- MLP (unchanged from R8) ----------------
#define MLP_SMEM 104448
__global__ __launch_bounds__(256, 2)
void k_mlp(const float* __restrict__ B1, const float* __restrict__ B2, const float* __restrict__ B3,
           const int* __restrict__ src_lv, const int* __restrict__ dpos_lv,
           const float* __restrict__ sb, const float* __restrict__ hb, int level, int Epad) {
    extern __shared__ char smc[];
    __nv_bfloat16* R0 = (__nv_bfloat16*)smc;
    __nv_bfloat16* R1 = (__nv_bfloat16*)(smc + 34816);
    __nv_bfloat16* Wbase = (__nv_bfloat16*)(smc + 69632);
    __shared__ int s_src[TILE_E], s_dp[TILE_E], s_meta[3];

    int tid = threadIdx.x;
    if (tid == 0) {
        int b = blockIdx.x, tot = g_etile[level][5], tc = -1, base = 0, ne = 0;
        if (b < tot) {
            int t2 = 0;
            while (b >= g_etile[level][t2 + 1]) t2++;
            base = g_eoff[level][t2] + (b - g_etile[level][t2]) * TILE_E;
            ne = min(TILE_E, g_eoff[level][t2] + g_ecnt[level][t2] - base);
            tc = t2;
        }
        s_meta[0] = tc; s_meta[1] = base; s_meta[2] = ne;
    }
    __syncthreads();
    int tc = s_meta[0];
    if (tc < 0) return;
    int base = s_meta[1], ne = s_meta[2], ti = c_TI[tc + 1];
    for (int i = tid; i < ne; i += 256) {
        int e = g_eperm[level * EMAX + base + i];
        s_src[i] = src_lv[level * Epad + e];
        s_dp[i] = dpos_lv[level * Epad + e];
    }
    __syncthreads();
    for (int i = tid; i < 64 * 256; i += 256) {
        int r = i >> 8, c = i & 255;
        float v = 0.f;
        if (r < ne) {
            int s = s_src[r];
            v = (c < 128) ? sb[s * Dh + c] : hb[s * Dh + (c - 128)];
        }
        splitbf(v, &R0[r * 264 + c], &R1[r * 264 + c]);
    }

    int lane = tid & 31, warp = tid >> 5, wr = warp >> 1, wc = warp & 1;
    float acc[8][4];

    auto prefW = [&](const __nv_bfloat16* gwh, const __nv_bfloat16* gwl, int kc, int buf) {
        __nv_bfloat16* Wb = Wbase + buf * 8704;
        #pragma unroll
        for (int j = 0; j < 2; j++) {
            int i2 = tid * 2 + j;
            int r = i2 >> 4, c8 = (i2 & 15) << 3;
            cpa16(Wb + r * 136 + c8, gwh + (kc + r) * 128 + c8);
            cpa16(Wb + 4352 + r * 136 + c8, gwl + (kc + r) * 128 + c8);
        }
        cp_commit();
    };

    auto run_gemm = [&](const __nv_bfloat16* sAh, const __nv_bfloat16* sAl, int lda, int K,
                        const __nv_bfloat16* gwh, const __nv_bfloat16* gwl) {
        #pragma unroll
        for (int t = 0; t < 8; t++) { acc[t][0] = acc[t][1] = acc[t][2] = acc[t][3] = 0.f; }
        int nch = K >> 5;
        prefW(gwh, gwl, 0, 0);
        for (int c = 0; c < nch; c++) {
            if (c + 1 < nch) { prefW(gwh, gwl, (c + 1) << 5, (c + 1) & 1); cp_wait<1>(); }
            else cp_wait<0>();
            __syncthreads();
            const __nv_bfloat16* Wb = Wbase + (c & 1) * 8704;
            int kc = c << 5;
            #pragma unroll
            for (int ks = 0; ks < 2; ks++) {
                int k0 = ks << 4;
                uint32_t ah[4], al[4];
                const __nv_bfloat16* ap = sAh + (wr * 16 + (lane & 15)) * lda + kc + k0 + ((lane >> 4) << 3);
                ldsm4(ah, ap);
                ldsm4(al, sAl + (ap - sAh));
                #pragma unroll
                for (int g = 0; g < 4; g++) {
                    int c0 = wc * 64 + (g << 4);
                    uint32_t bh[4], bl[4];
                    const __nv_bfloat16* bp = Wb + (k0 + (lane & 15)) * 136 + c0 + ((lane >> 4) << 3);
                    ldsm4t(bh, bp);
                    ldsm4t(bl, bp + 4352);
                    mma_bf(acc[2 * g], ah, bh[0], bh[1]);
                    mma_bf(acc[2 * g], ah, bl[0], bl[1]);
                    mma_bf(acc[2 * g], al, bh[0], bh[1]);
                    mma_bf(acc[2 * g + 1], ah, bh[2], bh[3]);
                    mma_bf(acc[2 * g + 1], ah, bl[2], bl[3]);
                    mma_bf(acc[2 * g + 1], al, bh[2], bh[3]);
                }
            }
            __syncthreads();
        }
    };

    int r1 = wr * 16 + (lane >> 2), r2 = r1 + 8;

    auto store_relu = [&](__nv_bfloat16* Dhp, __nv_bfloat16* Dlp, const float* bias) {
        #pragma unroll
        for (int t = 0; t < 8; t++) {
            int col = wc * 64 + t * 8 + ((lane & 3) << 1);
            float b0 = bias[col], b1 = bias[col + 1];
            splitbf(fmaxf(acc[t][0] + b0, 0.f), &Dhp[r1 * 136 + col], &Dlp[r1 * 136 + col]);
            splitbf(fmaxf(acc[t][1] + b1, 0.f), &Dhp[r1 * 136 + col + 1], &Dlp[r1 * 136 + col + 1]);
            splitbf(fmaxf(acc[t][2] + b0, 0.f), &Dhp[r2 * 136 + col], &Dlp[r2 * 136 + col]);
            splitbf(fmaxf(acc[t][3] + b1, 0.f), &Dhp[r2 * 136 + col + 1], &Dlp[r2 * 136 + col + 1]);
        }
    };

    run_gemm(R0, R1, 264, 256, g_W1h + ti * 32768, g_W1l + ti * 32768);
    store_relu(R0, R0 + 8704, B1 + ti * Dh);
    __syncthreads();
    run_gemm(R0, R0 + 8704, 136, 128, g_W2h + ti * 16384, g_W2l + ti * 16384);
    store_relu(R1, R1 + 8704, B2 + ti * Dh);
    __syncthreads();
    run_gemm(R1, R1 + 8704, 136, 128, g_W3h + ti * 16384, g_W3l + ti * 16384);
    {
        const float* bias = B3 + ti * Dh;
        #pragma unroll
        for (int t = 0; t < 8; t++) {
            int col = wc * 64 + t * 8 + ((lane & 3) << 1);
            float b0 = bias[col], b1 = bias[col + 1];
            if (r1 < ne) {
                float* mp = &g_msg[s_dp[r1] * Dh + col];
                atomicAdd(mp, acc[t][0] + b0);
                atomicAdd(mp + 1, acc[t][1] + b1);
            }
            if (r2 < ne) {
                float* mp = &g_msg[s_dp[r2] * Dh + col];
                atomicAdd(mp, acc[t][2] + b0);
                atomicAdd(mp + 1, acc[t][3] + b1);
            }
        }
    }
}

// ---------------- GRU: gates in registers, r/z fused into gi (64 live accs, no spills) ----------------
#define GRU_SMEM 84992
__global__ __launch_bounds__(256, 2)
void k_gru(const float* __restrict__ gbih, const float* __restrict__ gbhh,
           const int* __restrict__ node_lv, float* __restrict__ sb, float* __restrict__ hb,
           int level, int NP) {
    extern __shared__ char smc[];
    __nv_bfloat16* Xh = (__nv_bfloat16*)smc;
    __nv_bfloat16* Xl = (__nv_bfloat16*)(smc + 8704);
    __nv_bfloat16* Hh = (__nv_bfloat16*)(smc + 17408);
    __nv_bfloat16* Hl = (__nv_bfloat16*)(smc + 26112);
    __nv_bfloat16* Wbase = (__nv_bfloat16*)(smc + 34816);
    __shared__ int s_pos[TILE_G], s_node[TILE_G], s_meta[3];

    int tid = threadIdx.x;
    if (tid == 0) {
        int b = blockIdx.x, tot = g_ntile[level][5], tc = -1, base = 0, nn = 0;
        if (b < tot) {
            int t2 = 0;
            while (b >= g_ntile[level][t2 + 1]) t2++;
            base = g_noff[level][t2] + (b - g_ntile[level][t2]) * TILE_G;
            nn = min(TILE_G, g_noff[level][t2] + g_ncnt[level][t2] - base);
            tc = t2;
        }
        s_meta[0] = tc; s_meta[1] = base; s_meta[2] = nn;
    }
    __syncthreads();
    int tc = s_meta[0];
    if (tc < 0) return;
    int base = s_meta[1], nn = s_meta[2], ti = c_TI[tc + 1];
    for (int i = tid; i < nn; i += 256) {
        int p = g_nperm[level * NPMAX + base + i];
        s_pos[i] = p;
        s_node[i] = node_lv[level * NP + p];
    }
    __syncthreads();
    for (int i = tid; i < 32 * 128; i += 256) {
        int r = i >> 7, c = i & 127;
        float xv = 0.f, hv = 0.f;
        if (r < nn) {
            int p = s_pos[r];
            xv = g_msg[p * Dh + c];
            g_msg[p * Dh + c] = 0.f;
            hv = hb[s_node[r] * Dh + c];
        }
        splitbf(xv, &Xh[r * 136 + c], &Xl[r * 136 + c]);
        splitbf(hv, &Hh[r * 136 + c], &Hl[r * 136 + c]);
    }

    int lane = tid & 31, warp = tid >> 5, wr = warp >> 2, wc = warp & 3;
    int j0 = wc * 32;
    float gi[12][4], ghn[4][4];

    auto prefW = [&](const __nv_bfloat16* gwh, const __nv_bfloat16* gwl, int kc, int buf) {
        __nv_bfloat16* Wb = Wbase + buf * 12544;
        #pragma unroll
        for (int j = 0; j < 3; j++) {
            int i2 = tid * 3 + j;
            int r = i2 / 48, c8 = (i2 % 48) << 3;
            cpa16(Wb + r * 392 + c8, gwh + (kc + r) * 384 + c8);
            cpa16(Wb + 6272 + r * 392 + c8, gwl + (kc + r) * 384 + c8);
        }
        cp_commit();
    };

    // mode 0: X-gemm -> fill gi[0..11]. mode 1: H-gemm -> accumulate r/z into gi[0..7], n into ghn[0..3].
    auto run_gemm = [&](int mode, const __nv_bfloat16* sAh, const __nv_bfloat16* sAl,
                        const __nv_bfloat16* gwh, const __nv_bfloat16* gwl) {
        if (mode == 0) {
            #pragma unroll
            for (int t = 0; t < 12; t++) { gi[t][0] = gi[t][1] = gi[t][2] = gi[t][3] = 0.f; }
        } else {
            #pragma unroll
            for (int t = 0; t < 4; t++) { ghn[t][0] = ghn[t][1] = ghn[t][2] = ghn[t][3] = 0.f; }
        }
        prefW(gwh, gwl, 0, 0);
        for (int c = 0; c < 8; c++) {
            if (c < 7) { prefW(gwh, gwl, (c + 1) << 4, (c + 1) & 1); cp_wait<1>(); }
            else cp_wait<0>();
            __syncthreads();
            const __nv_bfloat16* Wb = Wbase + (c & 1) * 12544;
            uint32_t ah[4], al[4];
            const __nv_bfloat16* ap = sAh + (wr * 16 + (lane & 15)) * 136 + (c << 4) + ((lane >> 4) << 3);
            ldsm4(ah, ap);
            ldsm4(al, sAl + (ap - sAh));
            #pragma unroll
            for (int g = 0; g < 6; g++) {
                int c0 = (g >> 1) * 128 + j0 + ((g & 1) << 4);
                uint32_t bh[4], bl[4];
                const __nv_bfloat16* bp = Wb + (lane & 15) * 392 + c0 + ((lane >> 4) << 3);
                ldsm4t(bh, bp);
                ldsm4t(bl, bp + 6272);
                float* a0;
                float* a1;
                if (mode == 0 || g < 4) { a0 = gi[2 * g]; a1 = gi[2 * g + 1]; }
                else { a0 = ghn[2 * (g - 4)]; a1 = ghn[2 * (g - 4) + 1]; }
                mma_bf(a0, ah, bh[0], bh[1]);
                mma_bf(a0, ah, bl[0], bl[1]);
                mma_bf(a0, al, bh[0], bh[1]);
                mma_bf(a1, ah, bh[2], bh[3]);
                mma_bf(a1, ah, bl[2], bl[3]);
                mma_bf(a1, al, bh[2], bh[3]);
            }
            __syncthreads();
        }
    };

    int r1 = wr * 16 + (lane >> 2), r2 = r1 + 8;
    const __nv_bfloat16* Wihh = g_Wih_h + ti * 49152;
    const __nv_bfloat16* Wihl = g_Wih_l + ti * 49152;
    const float* bih = gbih + ti * 384;
    const float* bhh = gbhh + ti * 384;

    auto add_bih = [&]() {
        #pragma unroll
        for (int t = 0; t < 12; t++) {
            int col = (t >> 2) * 128 + j0 + (t & 3) * 8 + ((lane & 3) << 1);
            float b0 = bih[col], b1 = bih[col + 1];
            gi[t][0] += b0; gi[t][1] += b1; gi[t][2] += b0; gi[t][3] += b1;
        }
    };

    run_gemm(0, Xh, Xl, Wihh, Wihl);
    add_bih();

    int npass = (tc == 2) ? 2 : 1;   // AND also refreshes s
    for (int pass = 0; pass < npass; pass++) {
        if (pass == 1) {
            for (int i = tid; i < 32 * 128; i += 256) {
                int r = i >> 7, c = i & 127;
                float hv = (r < nn) ? sb[s_node[r] * Dh + c] : 0.f;
                splitbf(hv, &Hh[r * 136 + c], &Hl[r * 136 + c]);
            }
            __syncthreads();
            run_gemm(0, Xh, Xl, Wihh, Wihl);   // rebuild pristine gi (destroyed by pass-0 r/z fuse)
            add_bih();
        }
        run_gemm(1, Hh, Hl, g_Whh_h + ti * 49152, g_Whh_l + ti * 49152);
        {
            #pragma unroll
            for (int t = 0; t < 8; t++) {
                int col = (t >> 2) * 128 + j0 + (t & 3) * 8 + ((lane & 3) << 1);
                float b0 = bhh[col], b1 = bhh[col + 1];
                gi[t][0] += b0; gi[t][1] += b1; gi[t][2] += b0; gi[t][3] += b1;
            }
            #pragma unroll
            for (int t = 0; t < 4; t++) {
                int col = 256 + j0 + t * 8 + ((lane & 3) << 1);
                float b0 = bhh[col], b1 = bhh[col + 1];
                ghn[t][0] += b0; ghn[t][1] += b1; ghn[t][2] += b0; ghn[t][3] += b1;
            }
        }
        float* target = pass ? sb : hb;
        #pragma unroll
        for (int m = 0; m < 4; m++) {
            #pragma unroll
            for (int v = 0; v < 4; v++) {
                int row = (v < 2) ? r1 : r2;
                if (row < nn) {
                    int col = j0 + m * 8 + ((lane & 3) << 1) + (v & 1);
                    float rv = sigmf(gi[m][v]);
                    float zv = sigmf(gi[4 + m][v]);
                    float nv = tanhff(gi[8 + m][v] + rv * ghn[m][v]);
                    float h = __bfloat162float(Hh[row * 136 + col]) + __bfloat162float(Hl[row * 136 + col]);
                    target[s_node[row] * Dh + col] = (1.f - zv) * nv + zv * h;
                }
            }
        }
        __syncthreads();
    }
}

extern "C" void kernel_launch(void* const* d_in, const int* in_sizes, int n_in,
                              void* d_out, int out_size) {
    const float* x = (const float*)d_in[0];
    const float* Ws = (const float*)d_in[1];
    const float* Wt = (const float*)d_in[2];
    const float* aW1 = (const float*)d_in[3];
    const float* ab1 = (const float*)d_in[4];
    const float* aW2 = (const float*)d_in[5];
    const float* ab2 = (const float*)d_in[6];
    const float* aW3 = (const float*)d_in[7];
    const float* ab3 = (const float*)d_in[8];
    const float* gWih = (const float*)d_in[9];
    const float* gWhh = (const float*)d_in[10];
    const float* gbih = (const float*)d_in[11];
    const float* gbhh = (const float*)d_in[12];
    const int* src_lv = (const int*)d_in[13];
    const int* dpos_lv = (const int*)d_in[14];
    const int* egate_lv = (const int*)d_in[15];
    const int* node_lv = (const int*)d_in[16];
    const int* ngate_lv = (const int*)d_in[17];

    int N = in_sizes[0] / DINx;
    int Epad = in_sizes[13] / NLV;
    int NP = in_sizes[16] / NLV;

    float* sb = (float*)d_out;
    float* tb = sb + (size_t)N * Dh;
    float* hb = tb + (size_t)N * Dh;

    const int SM_SI = (4096 + 2 * 8192) * 4;
    cudaFuncSetAttribute(k_si, cudaFuncAttributeMaxDynamicSharedMemorySize, SM_SI);
    cudaFuncSetAttribute(k_mlp, cudaFuncAttributeMaxDynamicSharedMemorySize, MLP_SMEM);
    cudaFuncSetAttribute(k_gru, cudaFuncAttributeMaxDynamicSharedMemorySize, GRU_SMEM);

    int tot_cs = NLV * Epad + NLV * NP;
    int SC = (tot_cs + 255) / 256;
    int NB = (N + 63) / 64;

    k_prep<<<4096, 256>>>(aW1, aW2, aW3, gWih, gWhh);                           // 1
    k_countscan<<<SC, 256>>>(egate_lv, ngate_lv, Epad, NP);                     // 2
    k_si<<<SC + NB, 256, SM_SI>>>(egate_lv, ngate_lv, Epad, NP, SC,
                                  x, Ws, Wt, sb, tb, hb, N);                    // 3
    int mlp_grid = (Epad + TILE_E - 1) / TILE_E + 5;
    int gru_grid = (NP + TILE_G - 1) / TILE_G + 5;
    for (int l = 0; l < NLV; l++) {
        k_mlp<<<mlp_grid, 256, MLP_SMEM>>>(ab1, ab2, ab3, src_lv, dpos_lv, sb, hb, l, Epad);  // 4 = profiled
        k_gru<<<gru_grid, 256, GRU_SMEM>>>(gbih, gbhh, node_lv, sb, hb, l, NP);
    }
}

// round 10
// speedup vs baseline: 1.0060x; 1.0060x over previous
#include <cuda_runtime.h>
#include <cuda_bf16.h>
#include <cstdint>

#define Dh 128
#define DINx 64
#define NLV 15
#define EMAX 20480
#define NPMAX 8192
#define TILE_E 64
#define TILE_G 32

__device__ float g_msg[NPMAX * Dh];
__device__ int g_eperm[NLV * EMAX];
__device__ int g_nperm[NLV * NPMAX];
__device__ int g_ecnt[NLV][5], g_ncnt[NLV][5];
__device__ int g_ecur[NLV][5], g_ncur[NLV][5];
__device__ int g_eoff[NLV][5], g_noff[NLV][5];
__device__ int g_etile[NLV][6], g_ntile[NLV][6];
__device__ int g_done;

__device__ __nv_bfloat16 g_W1h[5 * 256 * 128], g_W1l[5 * 256 * 128];
__device__ __nv_bfloat16 g_W2h[5 * 128 * 128], g_W2l[5 * 128 * 128];
__device__ __nv_bfloat16 g_W3h[5 * 128 * 128], g_W3l[5 * 128 * 128];
__device__ __nv_bfloat16 g_Wih_h[5 * 128 * 384], g_Wih_l[5 * 128 * 384];
__device__ __nv_bfloat16 g_Whh_h[5 * 128 * 384], g_Whh_l[5 * 128 * 384];

__constant__ int c_TI[6] = {0, 3, 1, 0, 4, 2};

__device__ __forceinline__ float sigmf(float x) { return 1.f / (1.f + __expf(-x)); }
__device__ __forceinline__ float tanhff(float x) { float e = __expf(2.f * x); return 1.f - 2.f / (e + 1.f); }

__device__ __forceinline__ void splitbf(float v, __nv_bfloat16* h, __nv_bfloat16* l) {
    __nv_bfloat16 hh = __float2bfloat16_rn(v);
    *h = hh;
    *l = __float2bfloat16_rn(v - __bfloat162float(hh));
}

__device__ __forceinline__ void ldsm4(uint32_t r[4], const void* p) {
    unsigned int a = (unsigned int)__cvta_generic_to_shared(p);
    asm volatile("ldmatrix.sync.aligned.m8n8.x4.shared.b16 {%0,%1,%2,%3},[%4];"
                 : "=r"(r[0]), "=r"(r[1]), "=r"(r[2]), "=r"(r[3]) : "r"(a));
}
__device__ __forceinline__ void ldsm4t(uint32_t r[4], const void* p) {
    unsigned int a = (unsigned int)__cvta_generic_to_shared(p);
    asm volatile("ldmatrix.sync.aligned.m8n8.x4.trans.shared.b16 {%0,%1,%2,%3},[%4];"
                 : "=r"(r[0]), "=r"(r[1]), "=r"(r[2]), "=r"(r[3]) : "r"(a));
}
__device__ __forceinline__ void mma_bf(float c[4], const uint32_t a[4], uint32_t b0, uint32_t b1) {
    asm volatile(
        "mma.sync.aligned.m16n8k16.row.col.f32.bf16.bf16.f32 "
        "{%0,%1,%2,%3},{%4,%5,%6,%7},{%8,%9},{%0,%1,%2,%3};"
        : "+f"(c[0]), "+f"(c[1]), "+f"(c[2]), "+f"(c[3])
        : "r"(a[0]), "r"(a[1]), "r"(a[2]), "r"(a[3]), "r"(b0), "r"(b1));
}
__device__ __forceinline__ void cpa16(void* smem, const void* gmem) {
    unsigned int a = (unsigned int)__cvta_generic_to_shared(smem);
    asm volatile("cp.async.ca.shared.global [%0],[%1],16;" :: "r"(a), "l"(gmem));
}
__device__ __forceinline__ void cp_commit() { asm volatile("cp.async.commit_group;"); }
template<int N> __device__ __forceinline__ void cp_wait() { asm volatile("cp.async.wait_group %0;" :: "n"(N)); }

// ---------------- launch 1: zero + counters + weight split ----------------
__global__ __launch_bounds__(256) void k_prep(const float* __restrict__ aW1, const float* __restrict__ aW2,
                                              const float* __restrict__ aW3, const float* __restrict__ gWih,
                                              const float* __restrict__ gWhh) {
    int i = blockIdx.x * 256 + threadIdx.x;
    if (i == 0) g_done = 0;
    if (i < NPMAX * Dh) g_msg[i] = 0.f;
    if (i < NLV * 5) {
        ((int*)g_ecnt)[i] = 0; ((int*)g_ncnt)[i] = 0;
        ((int*)g_ecur)[i] = 0; ((int*)g_ncur)[i] = 0;
    }
    if (i < 163840) splitbf(aW1[i], &g_W1h[i], &g_W1l[i]);
    else if (i < 245760) { int j = i - 163840; splitbf(aW2[j], &g_W2h[j], &g_W2l[j]); }
    else if (i < 327680) { int j = i - 245760; splitbf(aW3[j], &g_W3h[j], &g_W3l[j]); }
    else if (i < 573440) { int j = i - 327680; splitbf(gWih[j], &g_Wih_h[j], &g_Wih_l[j]); }
    else if (i < 819200) { int j = i - 573440; splitbf(gWhh[j], &g_Whh_h[j], &g_Whh_l[j]); }
}

// ---------------- launch 2: count + (last block) scan ----------------
__global__ __launch_bounds__(256) void k_countscan(const int* __restrict__ eg, const int* __restrict__ ng, int Epad, int NP) {
    __shared__ int hist[150];
    __shared__ int s_ticket;
    int tid = threadIdx.x;
    if (tid < 150) hist[tid] = 0;
    __syncthreads();
    int i = blockIdx.x * 256 + tid;
    int ne = NLV * Epad;
    if (i < ne) {
        int g = eg[i];
        if (g > 0) atomicAdd(&hist[(i / Epad) * 5 + g - 1], 1);
    } else {
        int j = i - ne;
        if (j < NLV * NP) {
            int g = ng[j];
            if (g > 0) atomicAdd(&hist[75 + (j / NP) * 5 + g - 1], 1);
        }
    }
    __syncthreads();
    if (tid < 75 && hist[tid]) atomicAdd(&((int*)g_ecnt)[tid], hist[tid]);
    if (tid >= 75 && tid < 150 && hist[tid]) atomicAdd(&((int*)g_ncnt)[tid - 75], hist[tid]);
    __threadfence();
    __syncthreads();
    if (tid == 0) s_ticket = atomicAdd(&g_done, 1);
    __syncthreads();
    if (s_ticket == (int)gridDim.x - 1 && tid < NLV) {
        int l = tid;
        int off = 0, to = 0;
        for (int t = 0; t < 5; t++) {
            int cnt = atomicAdd(&g_ecnt[l][t], 0);
            g_eoff[l][t] = off; g_etile[l][t] = to;
            off += cnt; to += (cnt + TILE_E - 1) / TILE_E;
        }
        g_etile[l][5] = to;
        off = 0; to = 0;
        for (int t = 0; t < 5; t++) {
            int cnt = atomicAdd(&g_ncnt[l][t], 0);
            g_noff[l][t] = off; g_ntile[l][t] = to;
            off += cnt; to += (cnt + TILE_G - 1) / TILE_G;
        }
        g_ntile[l][5] = to;
    }
}

// ---------------- launch 3: fused scatter + input projections ----------------
__global__ __launch_bounds__(256)
void k_si(const int* __restrict__ eg, const int* __restrict__ ng, int Epad, int NP, int SC,
          const float* __restrict__ x, const float* __restrict__ Ws, const float* __restrict__ Wt,
          float* __restrict__ sb, float* __restrict__ tb, float* __restrict__ hb, int N) {
    extern __shared__ float smf[];
    int tid = threadIdx.x;
    if (blockIdx.x < SC) {
        int* hist = (int*)smf;
        int* basev = hist + 150;
        int* lcur = basev + 150;
        if (tid < 150) { hist[tid] = 0; lcur[tid] = 0; }
        __syncthreads();
        int i = blockIdx.x * 256 + tid;
        int ne = NLV * Epad;
        int bin = -1;
        if (i < ne) {
            int g = eg[i];
            if (g > 0) bin = (i / Epad) * 5 + g - 1;
        } else {
            int j = i - ne;
            if (j < NLV * NP) {
                int g = ng[j];
                if (g > 0) bin = 75 + (j / NP) * 5 + g - 1;
            }
        }
        if (bin >= 0) atomicAdd(&hist[bin], 1);
        __syncthreads();
        if (tid < 75 && hist[tid]) basev[tid] = atomicAdd(&((int*)g_ecur)[tid], hist[tid]);
        if (tid >= 75 && tid < 150 && hist[tid]) basev[tid] = atomicAdd(&((int*)g_ncur)[tid - 75], hist[tid]);
        __syncthreads();
        if (bin >= 0) {
            int p = basev[bin] + atomicAdd(&lcur[bin], 1);
            if (bin < 75) {
                int l = bin / 5;
                g_eperm[l * EMAX + ((int*)g_eoff)[bin] + p] = i % Epad;
            } else {
                int l = (bin - 75) / 5;
                g_nperm[l * NPMAX + ((int*)g_noff)[bin - 75] + p] = (i - ne) % NP;
            }
        }
        return;
    }
    // ---- input projection part ----
    float* smx = smf;
    float* sws = smf + 4096;
    float* swt = sws + 8192;
    int row0 = (blockIdx.x - SC) * 64;
    for (int i = tid; i < 8192; i += 256) { sws[i] = Ws[i]; swt[i] = Wt[i]; }
    for (int i = tid; i < 4096; i += 256) {
        int r = i >> 6, gr = row0 + r;
        smx[i] = (gr < N) ? x[gr * DINx + (i & 63)] : 0.f;
    }
    __syncthreads();
    int tx = tid & 31, ty = tid >> 5;
    float as[8][4] = {}, at[8][4] = {};
    #pragma unroll 4
    for (int k = 0; k < 64; k++) {
        float4 bs = *(float4*)&sws[k * 128 + tx * 4];
        float4 bt = *(float4*)&swt[k * 128 + tx * 4];
        #pragma unroll
        for (int r = 0; r < 8; r++) {
            float a = smx[(ty * 8 + r) * 64 + k];
            as[r][0] += a * bs.x; as[r][1] += a * bs.y; as[r][2] += a * bs.z; as[r][3] += a * bs.w;
            at[r][0] += a * bt.x; at[r][1] += a * bt.y; at[r][2] += a * bt.z; at[r][3] += a * bt.w;
        }
    }
    #pragma unroll
    for (int r = 0; r < 8; r++) {
        int gr = row0 + ty * 8 + r;
        if (gr < N) {
            *(float4*)&sb[gr * Dh + tx * 4] = make_float4(as[r][0], as[r][1], as[r][2], as[r][3]);
            *(float4*)&tb[gr * Dh + tx * 4] = make_float4(at[r][0], at[r][1], at[r][2], at[r][3]);
            *(float4*)&hb[gr * Dh + tx * 4] = make_float4(0.f, 0.f, 0.f, 0.f);
        }
    }
}

// ---------------- MLP (unchanged from R8) ----------------
#define MLP_SMEM 104448
__global__ __launch_bounds__(256, 2)
void k_mlp(const float* __restrict__ B1, const float* __restrict__ B2, const float* __restrict__ B3,
           const int* __restrict__ src_lv, const int* __restrict__ dpos_lv,
           const float* __restrict__ sb, const float* __restrict__ hb, int level, int Epad) {
    extern __shared__ char smc[];
    __nv_bfloat16* R0 = (__nv_bfloat16*)smc;
    __nv_bfloat16* R1 = (__nv_bfloat16*)(smc + 34816);
    __nv_bfloat16* Wbase = (__nv_bfloat16*)(smc + 69632);
    __shared__ int s_src[TILE_E], s_dp[TILE_E], s_meta[3];

    int tid = threadIdx.x;
    if (tid == 0) {
        int b = blockIdx.x, tot = g_etile[level][5], tc = -1, base = 0, ne = 0;
        if (b < tot) {
            int t2 = 0;
            while (b >= g_etile[level][t2 + 1]) t2++;
            base = g_eoff[level][t2] + (b - g_etile[level][t2]) * TILE_E;
            ne = min(TILE_E, g_eoff[level][t2] + g_ecnt[level][t2] - base);
            tc = t2;
        }
        s_meta[0] = tc; s_meta[1] = base; s_meta[2] = ne;
    }
    __syncthreads();
    int tc = s_meta[0];
    if (tc < 0) return;
    int base = s_meta[1], ne = s_meta[2], ti = c_TI[tc + 1];
    for (int i = tid; i < ne; i += 256) {
        int e = g_eperm[level * EMAX + base + i];
        s_src[i] = src_lv[level * Epad + e];
        s_dp[i] = dpos_lv[level * Epad + e];
    }
    __syncthreads();
    for (int i = tid; i < 64 * 256; i += 256) {
        int r = i >> 8, c = i & 255;
        float v = 0.f;
        if (r < ne) {
            int s = s_src[r];
            v = (c < 128) ? sb[s * Dh + c] : hb[s * Dh + (c - 128)];
        }
        splitbf(v, &R0[r * 264 + c], &R1[r * 264 + c]);
    }

    int lane = tid & 31, warp = tid >> 5, wr = warp >> 1, wc = warp & 1;
    float acc[8][4];

    auto prefW = [&](const __nv_bfloat16* gwh, const __nv_bfloat16* gwl, int kc, int buf) {
        __nv_bfloat16* Wb = Wbase + buf * 8704;
        #pragma unroll
        for (int j = 0; j < 2; j++) {
            int i2 = tid * 2 + j;
            int r = i2 >> 4, c8 = (i2 & 15) << 3;
            cpa16(Wb + r * 136 + c8, gwh + (kc + r) * 128 + c8);
            cpa16(Wb + 4352 + r * 136 + c8, gwl + (kc + r) * 128 + c8);
        }
        cp_commit();
    };

    auto run_gemm = [&](const __nv_bfloat16* sAh, const __nv_bfloat16* sAl, int lda, int K,
                        const __nv_bfloat16* gwh, const __nv_bfloat16* gwl) {
        #pragma unroll
        for (int t = 0; t < 8; t++) { acc[t][0] = acc[t][1] = acc[t][2] = acc[t][3] = 0.f; }
        int nch = K >> 5;
        prefW(gwh, gwl, 0, 0);
        for (int c = 0; c < nch; c++) {
            if (c + 1 < nch) { prefW(gwh, gwl, (c + 1) << 5, (c + 1) & 1); cp_wait<1>(); }
            else cp_wait<0>();
            __syncthreads();
            const __nv_bfloat16* Wb = Wbase + (c & 1) * 8704;
            int kc = c << 5;
            #pragma unroll
            for (int ks = 0; ks < 2; ks++) {
                int k0 = ks << 4;
                uint32_t ah[4], al[4];
                const __nv_bfloat16* ap = sAh + (wr * 16 + (lane & 15)) * lda + kc + k0 + ((lane >> 4) << 3);
                ldsm4(ah, ap);
                ldsm4(al, sAl + (ap - sAh));
                #pragma unroll
                for (int g = 0; g < 4; g++) {
                    int c0 = wc * 64 + (g << 4);
                    uint32_t bh[4], bl[4];
                    const __nv_bfloat16* bp = Wb + (k0 + (lane & 15)) * 136 + c0 + ((lane >> 4) << 3);
                    ldsm4t(bh, bp);
                    ldsm4t(bl, bp + 4352);
                    mma_bf(acc[2 * g], ah, bh[0], bh[1]);
                    mma_bf(acc[2 * g], ah, bl[0], bl[1]);
                    mma_bf(acc[2 * g], al, bh[0], bh[1]);
                    mma_bf(acc[2 * g + 1], ah, bh[2], bh[3]);
                    mma_bf(acc[2 * g + 1], ah, bl[2], bl[3]);
                    mma_bf(acc[2 * g + 1], al, bh[2], bh[3]);
                }
            }
            __syncthreads();
        }
    };

    int r1 = wr * 16 + (lane >> 2), r2 = r1 + 8;

    auto store_relu = [&](__nv_bfloat16* Dhp, __nv_bfloat16* Dlp, const float* bias) {
        #pragma unroll
        for (int t = 0; t < 8; t++) {
            int col = wc * 64 + t * 8 + ((lane & 3) << 1);
            float b0 = bias[col], b1 = bias[col + 1];
            splitbf(fmaxf(acc[t][0] + b0, 0.f), &Dhp[r1 * 136 + col], &Dlp[r1 * 136 + col]);
            splitbf(fmaxf(acc[t][1] + b1, 0.f), &Dhp[r1 * 136 + col + 1], &Dlp[r1 * 136 + col + 1]);
            splitbf(fmaxf(acc[t][2] + b0, 0.f), &Dhp[r2 * 136 + col], &Dlp[r2 * 136 + col]);
            splitbf(fmaxf(acc[t][3] + b1, 0.f), &Dhp[r2 * 136 + col + 1], &Dlp[r2 * 136 + col + 1]);
        }
    };

    run_gemm(R0, R1, 264, 256, g_W1h + ti * 32768, g_W1l + ti * 32768);
    store_relu(R0, R0 + 8704, B1 + ti * Dh);
    __syncthreads();
    run_gemm(R0, R0 + 8704, 136, 128, g_W2h + ti * 16384, g_W2l + ti * 16384);
    store_relu(R1, R1 + 8704, B2 + ti * Dh);
    __syncthreads();
    run_gemm(R1, R1 + 8704, 136, 128, g_W3h + ti * 16384, g_W3l + ti * 16384);
    {
        const float* bias = B3 + ti * Dh;
        #pragma unroll
        for (int t = 0; t < 8; t++) {
            int col = wc * 64 + t * 8 + ((lane & 3) << 1);
            float b0 = bias[col], b1 = bias[col + 1];
            if (r1 < ne) {
                float* mp = &g_msg[s_dp[r1] * Dh + col];
                atomicAdd(mp, acc[t][0] + b0);
                atomicAdd(mp + 1, acc[t][1] + b1);
            }
            if (r2 < ne) {
                float* mp = &g_msg[s_dp[r2] * Dh + col];
                atomicAdd(mp, acc[t][2] + b0);
                atomicAdd(mp + 1, acc[t][3] + b1);
            }
        }
    }
}

// ---------------- GRU: gates in registers, r/z fused into gi (64 live accs, no spills) ----------------
#define GRU_SMEM 84992
__global__ __launch_bounds__(256, 2)
void k_gru(const float* __restrict__ gbih, const float* __restrict__ gbhh,
           const int* __restrict__ node_lv, float* __restrict__ sb, float* __restrict__ hb,
           int level, int NP) {
    extern __shared__ char smc[];
    __nv_bfloat16* Xh = (__nv_bfloat16*)smc;
    __nv_bfloat16* Xl = (__nv_bfloat16*)(smc + 8704);
    __nv_bfloat16* Hh = (__nv_bfloat16*)(smc + 17408);
    __nv_bfloat16* Hl = (__nv_bfloat16*)(smc + 26112);
    __nv_bfloat16* Wbase = (__nv_bfloat16*)(smc + 34816);
    __shared__ int s_pos[TILE_G], s_node[TILE_G], s_meta[3];

    int tid = threadIdx.x;
    if (tid == 0) {
        int b = blockIdx.x, tot = g_ntile[level][5], tc = -1, base = 0, nn = 0;
        if (b < tot) {
            int t2 = 0;
            while (b >= g_ntile[level][t2 + 1]) t2++;
            base = g_noff[level][t2] + (b - g_ntile[level][t2]) * TILE_G;
            nn = min(TILE_G, g_noff[level][t2] + g_ncnt[level][t2] - base);
            tc = t2;
        }
        s_meta[0] = tc; s_meta[1] = base; s_meta[2] = nn;
    }
    __syncthreads();
    int tc = s_meta[0];
    if (tc < 0) return;
    int base = s_meta[1], nn = s_meta[2], ti = c_TI[tc + 1];
    for (int i = tid; i < nn; i += 256) {
        int p = g_nperm[level * NPMAX + base + i];
        s_pos[i] = p;
        s_node[i] = node_lv[level * NP + p];
    }
    __syncthreads();
    for (int i = tid; i < 32 * 128; i += 256) {
        int r = i >> 7, c = i & 127;
        float xv = 0.f, hv = 0.f;
        if (r < nn) {
            int p = s_pos[r];
            xv = g_msg[p * Dh + c];
            g_msg[p * Dh + c] = 0.f;
            hv = hb[s_node[r] * Dh + c];
        }
        splitbf(xv, &Xh[r * 136 + c], &Xl[r * 136 + c]);
        splitbf(hv, &Hh[r * 136 + c], &Hl[r * 136 + c]);
    }

    int lane = tid & 31, warp = tid >> 5, wr = warp >> 2, wc = warp & 3;
    int j0 = wc * 32;
    float gi[12][4], ghn[4][4];

    auto prefW = [&](const __nv_bfloat16* gwh, const __nv_bfloat16* gwl, int kc, int buf) {
        __nv_bfloat16* Wb = Wbase + buf * 12544;
        #pragma unroll
        for (int j = 0; j < 3; j++) {
            int i2 = tid * 3 + j;
            int r = i2 / 48, c8 = (i2 % 48) << 3;
            cpa16(Wb + r * 392 + c8, gwh + (kc + r) * 384 + c8);
            cpa16(Wb + 6272 + r * 392 + c8, gwl + (kc + r) * 384 + c8);
        }
        cp_commit();
    };

    // mode 0: X-gemm -> fill gi[0..11]. mode 1: H-gemm -> accumulate r/z into gi[0..7], n into ghn[0..3].
    auto run_gemm = [&](int mode, const __nv_bfloat16* sAh, const __nv_bfloat16* sAl,
                        const __nv_bfloat16* gwh, const __nv_bfloat16* gwl) {
        if (mode == 0) {
            #pragma unroll
            for (int t = 0; t < 12; t++) { gi[t][0] = gi[t][1] = gi[t][2] = gi[t][3] = 0.f; }
        } else {
            #pragma unroll
            for (int t = 0; t < 4; t++) { ghn[t][0] = ghn[t][1] = ghn[t][2] = ghn[t][3] = 0.f; }
        }
        prefW(gwh, gwl, 0, 0);
        for (int c = 0; c < 8; c++) {
            if (c < 7) { prefW(gwh, gwl, (c + 1) << 4, (c + 1) & 1); cp_wait<1>(); }
            else cp_wait<0>();
            __syncthreads();
            const __nv_bfloat16* Wb = Wbase + (c & 1) * 12544;
            uint32_t ah[4], al[4];
            const __nv_bfloat16* ap = sAh + (wr * 16 + (lane & 15)) * 136 + (c << 4) + ((lane >> 4) << 3);
            ldsm4(ah, ap);
            ldsm4(al, sAl + (ap - sAh));
            #pragma unroll
            for (int g = 0; g < 6; g++) {
                int c0 = (g >> 1) * 128 + j0 + ((g & 1) << 4);
                uint32_t bh[4], bl[4];
                const __nv_bfloat16* bp = Wb + (lane & 15) * 392 + c0 + ((lane >> 4) << 3);
                ldsm4t(bh, bp);
                ldsm4t(bl, bp + 6272);
                float* a0;
                float* a1;
                if (mode == 0 || g < 4) { a0 = gi[2 * g]; a1 = gi[2 * g + 1]; }
                else { a0 = ghn[2 * (g - 4)]; a1 = ghn[2 * (g - 4) + 1]; }
                mma_bf(a0, ah, bh[0], bh[1]);
                mma_bf(a0, ah, bl[0], bl[1]);
                mma_bf(a0, al, bh[0], bh[1]);
                mma_bf(a1, ah, bh[2], bh[3]);
                mma_bf(a1, ah, bl[2], bl[3]);
                mma_bf(a1, al, bh[2], bh[3]);
            }
            __syncthreads();
        }
    };

    int r1 = wr * 16 + (lane >> 2), r2 = r1 + 8;
    const __nv_bfloat16* Wihh = g_Wih_h + ti * 49152;
    const __nv_bfloat16* Wihl = g_Wih_l + ti * 49152;
    const float* bih = gbih + ti * 384;
    const float* bhh = gbhh + ti * 384;

    auto add_bih = [&]() {
        #pragma unroll
        for (int t = 0; t < 12; t++) {
            int col = (t >> 2) * 128 + j0 + (t & 3) * 8 + ((lane & 3) << 1);
            float b0 = bih[col], b1 = bih[col + 1];
            gi[t][0] += b0; gi[t][1] += b1; gi[t][2] += b0; gi[t][3] += b1;
        }
    };

    run_gemm(0, Xh, Xl, Wihh, Wihl);
    add_bih();

    int npass = (tc == 2) ? 2 : 1;   // AND also refreshes s
    for (int pass = 0; pass < npass; pass++) {
        if (pass == 1) {
            for (int i = tid; i < 32 * 128; i += 256) {
                int r = i >> 7, c = i & 127;
                float hv = (r < nn) ? sb[s_node[r] * Dh + c] : 0.f;
                splitbf(hv, &Hh[r * 136 + c], &Hl[r * 136 + c]);
            }
            __syncthreads();
            run_gemm(0, Xh, Xl, Wihh, Wihl);   // rebuild pristine gi (destroyed by pass-0 r/z fuse)
            add_bih();
        }
        run_gemm(1, Hh, Hl, g_Whh_h + ti * 49152, g_Whh_l + ti * 49152);
        {
            #pragma unroll
            for (int t = 0; t < 8; t++) {
                int col = (t >> 2) * 128 + j0 + (t & 3) * 8 + ((lane & 3) << 1);
                float b0 = bhh[col], b1 = bhh[col + 1];
                gi[t][0] += b0; gi[t][1] += b1; gi[t][2] += b0; gi[t][3] += b1;
            }
            #pragma unroll
            for (int t = 0; t < 4; t++) {
                int col = 256 + j0 + t * 8 + ((lane & 3) << 1);
                float b0 = bhh[col], b1 = bhh[col + 1];
                ghn[t][0] += b0; ghn[t][1] += b1; ghn[t][2] += b0; ghn[t][3] += b1;
            }
        }
        float* target = pass ? sb : hb;
        #pragma unroll
        for (int m = 0; m < 4; m++) {
            #pragma unroll
            for (int v = 0; v < 4; v++) {
                int row = (v < 2) ? r1 : r2;
                if (row < nn) {
                    int col = j0 + m * 8 + ((lane & 3) << 1) + (v & 1);
                    float rv = sigmf(gi[m][v]);
                    float zv = sigmf(gi[4 + m][v]);
                    float nv = tanhff(gi[8 + m][v] + rv * ghn[m][v]);
                    float h = __bfloat162float(Hh[row * 136 + col]) + __bfloat162float(Hl[row * 136 + col]);
                    target[s_node[row] * Dh + col] = (1.f - zv) * nv + zv * h;
                }
            }
        }
        __syncthreads();
    }
}

extern "C" void kernel_launch(void* const* d_in, const int* in_sizes, int n_in,
                              void* d_out, int out_size) {
    const float* x = (const float*)d_in[0];
    const float* Ws = (const float*)d_in[1];
    const float* Wt = (const float*)d_in[2];
    const float* aW1 = (const float*)d_in[3];
    const float* ab1 = (const float*)d_in[4];
    const float* aW2 = (const float*)d_in[5];
    const float* ab2 = (const float*)d_in[6];
    const float* aW3 = (const float*)d_in[7];
    const float* ab3 = (const float*)d_in[8];
    const float* gWih = (const float*)d_in[9];
    const float* gWhh = (const float*)d_in[10];
    const float* gbih = (const float*)d_in[11];
    const float* gbhh = (const float*)d_in[12];
    const int* src_lv = (const int*)d_in[13];
    const int* dpos_lv = (const int*)d_in[14];
    const int* egate_lv = (const int*)d_in[15];
    const int* node_lv = (const int*)d_in[16];
    const int* ngate_lv = (const int*)d_in[17];

    int N = in_sizes[0] / DINx;
    int Epad = in_sizes[13] / NLV;
    int NP = in_sizes[16] / NLV;

    float* sb = (float*)d_out;
    float* tb = sb + (size_t)N * Dh;
    float* hb = tb + (size_t)N * Dh;

    const int SM_SI = (4096 + 2 * 8192) * 4;
    cudaFuncSetAttribute(k_si, cudaFuncAttributeMaxDynamicSharedMemorySize, SM_SI);
    cudaFuncSetAttribute(k_mlp, cudaFuncAttributeMaxDynamicSharedMemorySize, MLP_SMEM);
    cudaFuncSetAttribute(k_gru, cudaFuncAttributeMaxDynamicSharedMemorySize, GRU_SMEM);

    int tot_cs = NLV * Epad + NLV * NP;
    int SC = (tot_cs + 255) / 256;
    int NB = (N + 63) / 64;

    k_prep<<<4096, 256>>>(aW1, aW2, aW3, gWih, gWhh);                           // 1
    k_countscan<<<SC, 256>>>(egate_lv, ngate_lv, Epad, NP);                     // 2
    k_si<<<SC + NB, 256, SM_SI>>>(egate_lv, ngate_lv, Epad, NP, SC,
                                  x, Ws, Wt, sb, tb, hb, N);                    // 3
    int mlp_grid = (Epad + TILE_E - 1) / TILE_E + 5;
    int gru_grid = (NP + TILE_G - 1) / TILE_G + 5;
    for (int l = 0; l < NLV; l++) {
        k_mlp<<<mlp_grid, 256, MLP_SMEM>>>(ab1, ab2, ab3, src_lv, dpos_lv, sb, hb, l, Epad);  // 4 = profiled
        k_gru<<<gru_grid, 256, GRU_SMEM>>>(gbih, gbhh, node_lv, sb, hb, l, NP);
    }
}